// round 10
// baseline (speedup 1.0000x reference)
#include <cuda_runtime.h>
#include <cstdint>

// PositionEncoding: out[b,s,d] = x[b,s,d] + pe[s,d]
//   pe[s,d] = sin(s / 10000^(d/D)) if d even else cos(s / 10000^(d/D))
// Shapes: B=8, S=4096, D=1024 (fp32).
//
// R10: controlled experiment — R3's two-group (4+4) pipeline structure with
// launch_bounds(256,6) for ~70% occupancy, but with PLAIN .cg cache ops.
// R3's regression is now attributed to its .cs streaming hints (R8 showed
// store hints alone cost ~4us); this isolates the structure variable:
// high occupancy + burst-grouped loads + unhinted stores.

static constexpr int B = 8;
static constexpr int S = 4096;
static constexpr int D = 1024;
static constexpr int D4 = D / 4;                  // 256 float4 per row
static constexpr int SD4 = S * D4;                // 1,048,576
static constexpr int BSTR = S * D4;               // batch stride (float4)

// log2(10000) / D  (D = 1024)
static constexpr float LOG2_10000_OVER_D = 13.287712379549449f / 1024.0f;

__global__ __launch_bounds__(256, 6)
void pe_add_kernel(const float4* __restrict__ x, float4* __restrict__ out) {
    int idx = blockIdx.x * 256 + threadIdx.x;     // grid exactly covers SD4

    const float4* __restrict__ xp = x + idx;
    float4* __restrict__ op = out + idx;

    // ---- group 0: batches 0..3, front-batched loads ----
    float4 v0 = __ldcg(xp + 0 * BSTR);
    float4 v1 = __ldcg(xp + 1 * BSTR);
    float4 v2 = __ldcg(xp + 2 * BSTR);
    float4 v3 = __ldcg(xp + 3 * BSTR);

    // ---- trig while group-0 loads are in flight ----
    int s  = idx >> 8;          // idx / D4
    int d4 = idx & (D4 - 1);    // idx % D4
    int d  = d4 << 2;
    float fs = (float)s;

    float a0 = fs * exp2f(-(float)(d + 0) * LOG2_10000_OVER_D);
    float a1 = fs * exp2f(-(float)(d + 1) * LOG2_10000_OVER_D);
    float a2 = fs * exp2f(-(float)(d + 2) * LOG2_10000_OVER_D);
    float a3 = fs * exp2f(-(float)(d + 3) * LOG2_10000_OVER_D);

    float pex = sinf(a0);   // even dim -> sin
    float pey = cosf(a1);   // odd dim  -> cos
    float pez = sinf(a2);
    float pew = cosf(a3);

    // ---- group 1 loads: batches 4..7 (overlap with group-0 stores) ----
    float4 w0 = __ldcg(xp + 4 * BSTR);
    float4 w1 = __ldcg(xp + 5 * BSTR);
    float4 w2 = __ldcg(xp + 6 * BSTR);
    float4 w3 = __ldcg(xp + 7 * BSTR);

    // ---- store group 0 ----
    v0.x += pex; v0.y += pey; v0.z += pez; v0.w += pew;
    __stcg(op + 0 * BSTR, v0);
    v1.x += pex; v1.y += pey; v1.z += pez; v1.w += pew;
    __stcg(op + 1 * BSTR, v1);
    v2.x += pex; v2.y += pey; v2.z += pez; v2.w += pew;
    __stcg(op + 2 * BSTR, v2);
    v3.x += pex; v3.y += pey; v3.z += pez; v3.w += pew;
    __stcg(op + 3 * BSTR, v3);

    // ---- store group 1 ----
    w0.x += pex; w0.y += pey; w0.z += pez; w0.w += pew;
    __stcg(op + 4 * BSTR, w0);
    w1.x += pex; w1.y += pey; w1.z += pez; w1.w += pew;
    __stcg(op + 5 * BSTR, w1);
    w2.x += pex; w2.y += pey; w2.z += pez; w2.w += pew;
    __stcg(op + 6 * BSTR, w2);
    w3.x += pex; w3.y += pey; w3.z += pez; w3.w += pew;
    __stcg(op + 7 * BSTR, w3);
}

extern "C" void kernel_launch(void* const* d_in, const int* in_sizes, int n_in,
                              void* d_out, int out_size) {
    const float4* x = (const float4*)d_in[0];
    float4* out = (float4*)d_out;

    int threads = 256;
    int blocks = SD4 / threads;   // 4096, exact
    pe_add_kernel<<<blocks, threads>>>(x, out);
}

// round 11
// speedup vs baseline: 1.0093x; 1.0093x over previous
#include <cuda_runtime.h>
#include <cstdint>

// PositionEncoding: out[b,s,d] = x[b,s,d] + pe[s,d]
//   pe[s,d] = sin(s / 10000^(d/D)) if d even else cos(s / 10000^(d/D))
// Shapes: B=8, S=4096, D=1024 (fp32).
//
// R11: 256-bit (v8.b32) global accesses — sm_103a supports 32B ld/st.
// One warp instruction moves 1024B = 8 full cache lines -> longer DRAM
// bursts, half the LSU instructions. Each thread owns (s, 8-float d-chunk)
// for a group of 4 batches (batch split across threads keeps regs ~65,
// occ ~40%). Structure: 4 front-batched v8 loads, trig overlapped, 4 v8
// stores — no load/store interleaving (R10 lesson), no cache hints
// (R3/R8/R9 lessons).

static constexpr int S = 4096;
static constexpr int D = 1024;
static constexpr int D8 = D / 8;                  // 128 float8-chunks per row
static constexpr int SD8 = S * D8;                // 524,288 chunk positions
static constexpr int BSTR8 = S * D8;              // batch stride in float8 units
static constexpr int WORK = SD8 * 2;              // x2 batch groups = 1,048,576

// log2(10000) / D  (D = 1024)
static constexpr float LOG2_10000_OVER_D = 13.287712379549449f / 1024.0f;

struct f8 { float v[8]; };

__device__ __forceinline__ f8 ldg256(const float* p) {
    f8 r;
    asm volatile("ld.global.nc.v8.b32 {%0,%1,%2,%3,%4,%5,%6,%7}, [%8];"
                 : "=f"(r.v[0]), "=f"(r.v[1]), "=f"(r.v[2]), "=f"(r.v[3]),
                   "=f"(r.v[4]), "=f"(r.v[5]), "=f"(r.v[6]), "=f"(r.v[7])
                 : "l"(p));
    return r;
}

__device__ __forceinline__ void stg256(float* p, const f8& r) {
    asm volatile("st.global.cg.v8.b32 [%0], {%1,%2,%3,%4,%5,%6,%7,%8};"
                 :: "l"(p),
                    "f"(r.v[0]), "f"(r.v[1]), "f"(r.v[2]), "f"(r.v[3]),
                    "f"(r.v[4]), "f"(r.v[5]), "f"(r.v[6]), "f"(r.v[7])
                 : "memory");
}

__global__ __launch_bounds__(256)
void pe_add_kernel(const float* __restrict__ x, float* __restrict__ out) {
    int idx = blockIdx.x * 256 + threadIdx.x;     // grid exactly covers WORK

    int pos = idx & (SD8 - 1);      // (s, d8) chunk position
    int bg  = idx >> 19;            // batch group: 0 -> batches 0..3, 1 -> 4..7

    int s   = pos >> 7;             // pos / D8
    int d8c = pos & (D8 - 1);       // pos % D8
    int d   = d8c << 3;

    // byte-element base: (bg*4 batches) * stride + chunk
    long long base = (long long)(bg * 4) * ((long long)BSTR8 * 8) + (long long)pos * 8;
    const float* xp = x + base;
    float* op = out + base;
    const long long BS = (long long)BSTR8 * 8;    // batch stride in floats

    // ---- 4 front-batched 32B loads (one per batch in this group) ----
    f8 a = ldg256(xp + 0 * BS);
    f8 b = ldg256(xp + 1 * BS);
    f8 c = ldg256(xp + 2 * BS);
    f8 e = ldg256(xp + 3 * BS);

    // ---- trig for 8 dims while loads are in flight ----
    float fs = (float)s;
    float pe[8];
#pragma unroll
    for (int j = 0; j < 8; j++) {
        float ang = fs * exp2f(-(float)(d + j) * LOG2_10000_OVER_D);
        pe[j] = (j & 1) ? cosf(ang) : sinf(ang);   // even dim -> sin, odd -> cos
    }

    // ---- add + 4 front-batched 32B stores ----
#pragma unroll
    for (int j = 0; j < 8; j++) a.v[j] += pe[j];
    stg256(op + 0 * BS, a);
#pragma unroll
    for (int j = 0; j < 8; j++) b.v[j] += pe[j];
    stg256(op + 1 * BS, b);
#pragma unroll
    for (int j = 0; j < 8; j++) c.v[j] += pe[j];
    stg256(op + 2 * BS, c);
#pragma unroll
    for (int j = 0; j < 8; j++) e.v[j] += pe[j];
    stg256(op + 3 * BS, e);
}

extern "C" void kernel_launch(void* const* d_in, const int* in_sizes, int n_in,
                              void* d_out, int out_size) {
    const float* x = (const float*)d_in[0];
    float* out = (float*)d_out;

    int threads = 256;
    int blocks = WORK / threads;   // 4096, exact
    pe_add_kernel<<<blocks, threads>>>(x, out);
}

// round 12
// speedup vs baseline: 1.0368x; 1.0272x over previous
#include <cuda_runtime.h>
#include <cstdint>

// PositionEncoding: out[b,s,d] = x[b,s,d] + pe[s,d]
//   pe[s,d] = sin(s / 10000^(d/D)) if d even else cos(s / 10000^(d/D))
// Shapes: B=8, S=4096, D=1024 (fp32).
//
// R12: TMA bulk stores to de-fragment the DRAM write stream. Reads stay
// R6's proven 8-deep front-batched ldcg; results are staged in smem and
// each batch's 4KB output chunk is emitted as ONE cp.async.bulk
// (shared->global), so writes reach DRAM as dense contiguous bursts
// instead of interleaved 128B warp sectors. Hypothesis: fewer read/write
// bus turnarounds -> higher DRAM busy.

static constexpr int B = 8;
static constexpr int S = 4096;
static constexpr int D = 1024;
static constexpr int D4 = D / 4;                  // 256 float4 per row
static constexpr int SD4 = S * D4;                // 1,048,576
static constexpr int BSTR = S * D4;               // batch stride (float4)

// log2(10000) / D  (D = 1024)
static constexpr float LOG2_10000_OVER_D = 13.287712379549449f / 1024.0f;

__global__ __launch_bounds__(256)
void pe_add_kernel(const float4* __restrict__ x, float4* __restrict__ out) {
    __shared__ float4 buf[B * 256];               // 32 KB staging

    int t = threadIdx.x;
    int idx = blockIdx.x * 256 + t;               // grid exactly covers SD4

    // ---- issue all 8 loads first (front-batched LDG.128, MLP=8) ----
    float4 v[B];
#pragma unroll
    for (int b = 0; b < B; b++) {
        v[b] = __ldcg(&x[idx + b * BSTR]);
    }

    // ---- compute PE while the loads are in flight ----
    int s  = idx >> 8;          // idx / D4
    int d4 = idx & (D4 - 1);    // idx % D4
    int d  = d4 << 2;
    float fs = (float)s;

    float a0 = fs * exp2f(-(float)(d + 0) * LOG2_10000_OVER_D);
    float a1 = fs * exp2f(-(float)(d + 1) * LOG2_10000_OVER_D);
    float a2 = fs * exp2f(-(float)(d + 2) * LOG2_10000_OVER_D);
    float a3 = fs * exp2f(-(float)(d + 3) * LOG2_10000_OVER_D);

    float pex = sinf(a0);   // even dim -> sin
    float pey = cosf(a1);   // odd dim  -> cos
    float pez = sinf(a2);
    float pew = cosf(a3);

    // ---- add, stage results in smem (per-batch contiguous 4KB chunks) ----
#pragma unroll
    for (int b = 0; b < B; b++) {
        float4 o;
        o.x = v[b].x + pex;
        o.y = v[b].y + pey;
        o.z = v[b].z + pez;
        o.w = v[b].w + pew;
        buf[b * 256 + t] = o;
    }
    __syncthreads();

    // ---- make smem writes visible to the async proxy, then bulk-store ----
    asm volatile("fence.proxy.async.shared::cta;" ::: "memory");

    if (t == 0) {
        int base = blockIdx.x * 256;
#pragma unroll
        for (int b = 0; b < B; b++) {
            unsigned sptr = (unsigned)__cvta_generic_to_shared(&buf[b * 256]);
            const float4* gptr = out + ((long long)b * BSTR + base);
            asm volatile(
                "cp.async.bulk.global.shared::cta.bulk_group [%0], [%1], %2;"
                :: "l"(gptr), "r"(sptr), "n"(256 * 16)
                : "memory");
        }
        asm volatile("cp.async.bulk.commit_group;" ::: "memory");
        // Drain before CTA exit (smem is reclaimed at exit).
        asm volatile("cp.async.bulk.wait_group 0;" ::: "memory");
    }
}

extern "C" void kernel_launch(void* const* d_in, const int* in_sizes, int n_in,
                              void* d_out, int out_size) {
    const float4* x = (const float4*)d_in[0];
    float4* out = (float4*)d_out;

    int threads = 256;
    int blocks = SD4 / threads;   // 4096, exact
    pe_add_kernel<<<blocks, threads>>>(x, out);
}